// round 1
// baseline (speedup 1.0000x reference)
#include <cuda_runtime.h>
#include <cstddef>

// ---------------------------------------------------------------------------
// SageLayer fused pipeline
//   out[b] = normalize(leaky( X[nodes] @ A^T + c ))[nodes_idx]
// where X[u] = [ emb[uid[u]] | mean_k emb[adj[u,k]] | mean_k emb[dis[u,k]] ]
// and A, c are folded from all the small weight matrices (exact algebra).
// ---------------------------------------------------------------------------

#define U_NODES 16384
#define K_NEIGH 32
#define D_IN    128
#define D_OUT   384
#define B_OUT   32768

// ---- device scratch (allocation-free rule: __device__ globals) ----
__device__ __align__(16) float g_Padj[128 * 128];
__device__ __align__(16) float g_Pdis[128 * 128];
__device__ __align__(16) float g_qadj[128];
__device__ __align__(16) float g_qdis[128];
__device__ __align__(16) float g_At[384 * 384];     // At[k][n] = A[n][k]
__device__ __align__(16) float g_c[384];
__device__ __align__(16) float g_X[(size_t)U_NODES * 384];
__device__ __align__(16) float g_Y[(size_t)U_NODES * 384];

// ---- packed f32x2 helpers (Blackwell) ----
__device__ __forceinline__ unsigned long long pack2(float lo, float hi) {
    unsigned long long r;
    asm("mov.b64 %0, {%1, %2};" : "=l"(r) : "f"(lo), "f"(hi));
    return r;
}
__device__ __forceinline__ unsigned long long fma2(unsigned long long a,
                                                   unsigned long long b,
                                                   unsigned long long c) {
    unsigned long long d;
    asm("fma.rn.f32x2 %0, %1, %2, %3;" : "=l"(d) : "l"(a), "l"(b), "l"(c));
    return d;
}
__device__ __forceinline__ float2 unpack2(unsigned long long v) {
    float2 f;
    asm("mov.b64 {%0, %1}, %2;" : "=f"(f.x), "=f"(f.y) : "l"(v));
    return f;
}

// ---------------------------------------------------------------------------
// fold1: P = W @ Wa  (128x128), q = W @ ba   for adj (blockIdx.y=0) / dis (=1)
// ---------------------------------------------------------------------------
__global__ void fold1_kernel(const float* __restrict__ W_adj,
                             const float* __restrict__ Wa_adj,
                             const float* __restrict__ ba_adj,
                             const float* __restrict__ W_dis,
                             const float* __restrict__ Wa_dis,
                             const float* __restrict__ ba_dis) {
    const int g = blockIdx.x;          // 0..127
    const int which = blockIdx.y;      // 0=adj, 1=dis
    const int d = threadIdx.x;         // 0..127

    const float* W  = which ? W_dis  : W_adj;
    const float* Wa = which ? Wa_dis : Wa_adj;
    const float* ba = which ? ba_dis : ba_adj;
    float* P = which ? g_Pdis : g_Padj;
    float* q = which ? g_qdis : g_qadj;

    float acc = 0.f;
#pragma unroll 8
    for (int e = 0; e < 128; e++)
        acc += W[g * 128 + e] * Wa[e * 128 + d];
    P[g * 128 + d] = acc;

    __shared__ float red[128];
    red[d] = W[g * 128 + d] * ba[d];
    __syncthreads();
#pragma unroll
    for (int s = 64; s > 0; s >>= 1) {
        if (d < s) red[d] += red[d + s];
        __syncthreads();
    }
    if (d == 0) q[g] = red[0];
}

// ---------------------------------------------------------------------------
// fold2: A[n][k] folded 384x384 (stored transposed as At[k][n]), c[n]
// grid = 384 blocks (one per n), 384 threads (one per k)
// ---------------------------------------------------------------------------
__global__ void fold2_kernel(const float* __restrict__ WC,
                             const float* __restrict__ W_self,
                             const float* __restrict__ bWC,
                             const float* __restrict__ bias) {
    const int n = blockIdx.x;
    const int k = threadIdx.x;

    float acc = 0.f;
    if (k < 128) {
#pragma unroll 8
        for (int e = 0; e < 128; e++)
            acc += WC[n * 384 + e] * W_self[e * 128 + k];
    } else if (k < 256) {
        const int kk = k - 128;
#pragma unroll 8
        for (int g = 0; g < 128; g++)
            acc += WC[n * 384 + 128 + g] * g_Padj[g * 128 + kk];
    } else {
        const int kk = k - 256;
#pragma unroll 8
        for (int g = 0; g < 128; g++)
            acc += WC[n * 384 + 256 + g] * g_Pdis[g * 128 + kk];
    }
    g_At[k * 384 + n] = acc;

    // constant vector c[n]
    float cp = 0.f;
    if (k >= 128 && k < 256) cp = WC[n * 384 + k] * g_qadj[k - 128];
    else if (k >= 256)       cp = WC[n * 384 + k] * g_qdis[k - 256];

    __shared__ float red[384];
    red[k] = cp;
    __syncthreads();
    if (k < 128) red[k] = red[k] + red[k + 128] + red[k + 256];
    __syncthreads();
#pragma unroll
    for (int s = 64; s > 0; s >>= 1) {
        if (k < s) red[k] += red[k + s];
        __syncthreads();
    }
    if (k == 0) g_c[n] = red[0] + bWC[n] + bias[n];
}

// ---------------------------------------------------------------------------
// gather_mean: X[u] = [ emb[uid[u]] | mean(adj rows) | mean(dis rows) ]
// 16384 blocks x 128 threads; thread t owns dim t. Warp lanes span consecutive
// dims -> every row read is 4x128B fully-coalesced lines; 64 independent rows
// per CTA gives deep MLP. This kernel carries the DRAM roofline (~537 MB).
// ---------------------------------------------------------------------------
__global__ void gather_mean_kernel(const float* __restrict__ emb,
                                   const int* __restrict__ uid,
                                   const int* __restrict__ adj,
                                   const int* __restrict__ dis) {
    const int u = blockIdx.x;
    const int t = threadIdx.x;

    __shared__ int sa[K_NEIGH];
    __shared__ int sd[K_NEIGH];
    __shared__ int sself;
    if (t < 32)       sa[t]      = adj[u * K_NEIGH + t];
    else if (t < 64)  sd[t - 32] = dis[u * K_NEIGH + (t - 32)];
    else if (t == 64) sself      = uid[u];
    __syncthreads();

    float acc_a = 0.f, acc_d = 0.f;
#pragma unroll
    for (int k = 0; k < K_NEIGH; k++) {
        acc_a += emb[(size_t)sa[k] * D_IN + t];
        acc_d += emb[(size_t)sd[k] * D_IN + t];
    }
    const float selfv = emb[(size_t)sself * D_IN + t];

    float* xr = g_X + (size_t)u * 384;
    xr[t]       = selfv;
    xr[128 + t] = acc_a * (1.0f / 32.0f);
    xr[256 + t] = acc_d * (1.0f / 32.0f);
}

// ---------------------------------------------------------------------------
// GEMM: Y = leaky( X[16384,384] @ At + c )   (At is [K=384][N=384])
// 128x128x32 tiles, 256 threads, 8x8 microtile, packed fma.rn.f32x2
// ---------------------------------------------------------------------------
__global__ __launch_bounds__(256, 2) void gemm_kernel() {
    __shared__ float As[32 * 132];   // As[k][m], padded stride 132
    __shared__ float Bs[32 * 128];   // Bs[k][n]

    const int t  = threadIdx.x;
    const int m0 = blockIdx.y * 128;
    const int n0 = blockIdx.x * 128;
    const int tm = (t >> 4) << 3;    // 0..120
    const int tn = (t & 15) << 3;    // 0..120

    unsigned long long acc[8][4];
#pragma unroll
    for (int i = 0; i < 8; i++)
#pragma unroll
        for (int j = 0; j < 4; j++) acc[i][j] = 0ULL;

    const float4* Xv = (const float4*)g_X;
    const float4* Av = (const float4*)g_At;

    for (int kt = 0; kt < 12; kt++) {
        // load X tile -> As (transposed to k-major-by-m)
#pragma unroll
        for (int i = 0; i < 4; i++) {
            const int lin = i * 256 + t;
            const int m = lin >> 3;        // 0..127
            const int q = lin & 7;         // float4 index within 32-wide k slab
            float4 v = Xv[(size_t)(m0 + m) * 96 + kt * 8 + q];
            const int kb = q * 4;
            As[(kb + 0) * 132 + m] = v.x;
            As[(kb + 1) * 132 + m] = v.y;
            As[(kb + 2) * 132 + m] = v.z;
            As[(kb + 3) * 132 + m] = v.w;
        }
        // load At tile -> Bs (direct, vectorized)
#pragma unroll
        for (int i = 0; i < 4; i++) {
            const int lin = i * 256 + t;
            const int kk = lin >> 5;       // 0..31
            const int nq = lin & 31;       // float4 within 128-wide n slab
            float4 v = Av[(size_t)(kt * 32 + kk) * 96 + (n0 >> 2) + nq];
            *(float4*)&Bs[kk * 128 + nq * 4] = v;
        }
        __syncthreads();

#pragma unroll 8
        for (int k = 0; k < 32; k++) {
            float4 a0 = *(const float4*)&As[k * 132 + tm];
            float4 a1 = *(const float4*)&As[k * 132 + tm + 4];
            float4 b0 = *(const float4*)&Bs[k * 128 + tn];
            float4 b1 = *(const float4*)&Bs[k * 128 + tn + 4];
            unsigned long long bp0 = pack2(b0.x, b0.y);
            unsigned long long bp1 = pack2(b0.z, b0.w);
            unsigned long long bp2 = pack2(b1.x, b1.y);
            unsigned long long bp3 = pack2(b1.z, b1.w);
            const float av[8] = {a0.x, a0.y, a0.z, a0.w, a1.x, a1.y, a1.z, a1.w};
#pragma unroll
            for (int i = 0; i < 8; i++) {
                unsigned long long ad = pack2(av[i], av[i]);
                acc[i][0] = fma2(ad, bp0, acc[i][0]);
                acc[i][1] = fma2(ad, bp1, acc[i][1]);
                acc[i][2] = fma2(ad, bp2, acc[i][2]);
                acc[i][3] = fma2(ad, bp3, acc[i][3]);
            }
        }
        __syncthreads();
    }

    float cr[8];
#pragma unroll
    for (int j = 0; j < 8; j++) cr[j] = g_c[n0 + tn + j];

#pragma unroll
    for (int i = 0; i < 8; i++) {
        float2 p0 = unpack2(acc[i][0]);
        float2 p1 = unpack2(acc[i][1]);
        float2 p2 = unpack2(acc[i][2]);
        float2 p3 = unpack2(acc[i][3]);
        float v[8] = {p0.x, p0.y, p1.x, p1.y, p2.x, p2.y, p3.x, p3.y};
#pragma unroll
        for (int j = 0; j < 8; j++) {
            float y = v[j] + cr[j];
            v[j] = (y > 0.f) ? y : 0.2f * y;   // leaky_relu(0.2)
        }
        float4* o = (float4*)&g_Y[(size_t)(m0 + tm + i) * 384 + n0 + tn];
        o[0] = make_float4(v[0], v[1], v[2], v[3]);
        o[1] = make_float4(v[4], v[5], v[6], v[7]);
    }
}

// ---------------------------------------------------------------------------
// norm_gather: out[b] = Y[nodes_idx[b]] / max(||Y[nodes_idx[b]]||, 1e-12)
// one warp per output row; Y fits in L2 so duplicate rows are cheap.
// ---------------------------------------------------------------------------
__global__ void norm_gather_kernel(const int* __restrict__ nodes_idx,
                                   float* __restrict__ out) {
    const int w = threadIdx.x >> 5;
    const int l = threadIdx.x & 31;
    const int b = blockIdx.x * 8 + w;
    const int u = nodes_idx[b];

    const float4* yr = (const float4*)(g_Y + (size_t)u * 384);
    float4 v0 = yr[l];
    float4 v1 = yr[l + 32];
    float4 v2 = yr[l + 64];

    float s = v0.x * v0.x + v0.y * v0.y + v0.z * v0.z + v0.w * v0.w
            + v1.x * v1.x + v1.y * v1.y + v1.z * v1.z + v1.w * v1.w
            + v2.x * v2.x + v2.y * v2.y + v2.z * v2.z + v2.w * v2.w;
#pragma unroll
    for (int off = 16; off > 0; off >>= 1)
        s += __shfl_xor_sync(0xffffffffu, s, off);

    const float inv = 1.0f / fmaxf(sqrtf(s), 1e-12f);

    float4* o = (float4*)(out + (size_t)b * 384);
    v0.x *= inv; v0.y *= inv; v0.z *= inv; v0.w *= inv;
    v1.x *= inv; v1.y *= inv; v1.z *= inv; v1.w *= inv;
    v2.x *= inv; v2.y *= inv; v2.z *= inv; v2.w *= inv;
    o[l]      = v0;
    o[l + 32] = v1;
    o[l + 64] = v2;
}

// ---------------------------------------------------------------------------
extern "C" void kernel_launch(void* const* d_in, const int* in_sizes, int n_in,
                              void* d_out, int out_size) {
    const float* emb    = (const float*)d_in[0];
    const float* Wa_adj = (const float*)d_in[1];
    const float* ba_adj = (const float*)d_in[2];
    const float* Wa_dis = (const float*)d_in[3];
    const float* ba_dis = (const float*)d_in[4];
    const float* W_self = (const float*)d_in[5];
    const float* W_adj  = (const float*)d_in[6];
    const float* W_dis  = (const float*)d_in[7];
    const float* WC     = (const float*)d_in[8];
    const float* bWC    = (const float*)d_in[9];
    const float* bias   = (const float*)d_in[10];
    const int* uid      = (const int*)d_in[11];
    const int* adj      = (const int*)d_in[12];
    const int* dis      = (const int*)d_in[13];
    const int* nidx     = (const int*)d_in[14];
    float* out          = (float*)d_out;

    fold1_kernel<<<dim3(128, 2), 128>>>(W_adj, Wa_adj, ba_adj,
                                        W_dis, Wa_dis, ba_dis);
    gather_mean_kernel<<<U_NODES, 128>>>(emb, uid, adj, dis);
    fold2_kernel<<<384, 384>>>(WC, W_self, bWC, bias);
    gemm_kernel<<<dim3(3, 128), 256>>>();
    norm_gather_kernel<<<B_OUT / 8, 256>>>(nidx, out);
}

// round 3
// speedup vs baseline: 1.3108x; 1.3108x over previous
#include <cuda_runtime.h>
#include <cuda_bf16.h>
#include <cstdint>
#include <cstddef>

// ---------------------------------------------------------------------------
// SageLayer fused pipeline (HMMA mma.sync bf16x3 GEMM — plain sm_103 target,
// tcgen05 is unavailable because the harness PTX stage is compute_103).
//   out[b] = normalize(leaky( X @ A^T + c ))[nodes_idx]
//   X[u] = [ emb[uid[u]] | mean_k emb[adj[u,k]] | mean_k emb[dis[u,k]] ]
//   A, c folded from all small weight matrices (exact algebra).
//   GEMM: fp32 via bf16 split: hi*hi + hi*lo + lo*hi, fp32 HMMA accumulators.
// ---------------------------------------------------------------------------

#define U_NODES 16384
#define K_NEIGH 32
#define D_IN    128
#define D_OUT   384
#define B_OUT   32768

// ---- device scratch ----
__device__ __align__(16) float g_Padj[128 * 128];
__device__ __align__(16) float g_Pdis[128 * 128];
__device__ __align__(16) float g_qadj[128];
__device__ __align__(16) float g_qdis[128];
__device__ __align__(16) float g_c[384];
__device__ __align__(16) __nv_bfloat16 g_Xhi[(size_t)U_NODES * 384];
__device__ __align__(16) __nv_bfloat16 g_Xlo[(size_t)U_NODES * 384];
__device__ __align__(16) __nv_bfloat16 g_Bhi[384 * 384];   // folded A[n][k]
__device__ __align__(16) __nv_bfloat16 g_Blo[384 * 384];
__device__ __align__(16) float g_Y[(size_t)U_NODES * 384];

// ---- helpers ----
__device__ __forceinline__ uint32_t smem_u32(const void* p) {
    uint32_t a;
    asm("{ .reg .u64 t; cvta.to.shared.u64 t, %1; cvt.u32.u64 %0, t; }"
        : "=r"(a) : "l"(p));
    return a;
}
__device__ __forceinline__ void cp_async16(uint32_t dst, const void* src) {
    asm volatile("cp.async.cg.shared.global [%0], [%1], 16;"
                 :: "r"(dst), "l"(src) : "memory");
}
__device__ __forceinline__ void cp_commit() {
    asm volatile("cp.async.commit_group;" ::: "memory");
}
template <int N>
__device__ __forceinline__ void cp_wait() {
    asm volatile("cp.async.wait_group %0;" :: "n"(N) : "memory");
}
__device__ __forceinline__ void ldsm_x4(uint32_t& r0, uint32_t& r1,
                                        uint32_t& r2, uint32_t& r3, uint32_t a) {
    asm volatile("ldmatrix.sync.aligned.m8n8.x4.shared.b16 {%0,%1,%2,%3}, [%4];"
                 : "=r"(r0), "=r"(r1), "=r"(r2), "=r"(r3) : "r"(a));
}
__device__ __forceinline__ void mma16816(float& c0, float& c1, float& c2, float& c3,
                                         uint32_t a0, uint32_t a1, uint32_t a2, uint32_t a3,
                                         uint32_t b0, uint32_t b1) {
    asm volatile(
        "mma.sync.aligned.m16n8k16.row.col.f32.bf16.bf16.f32 "
        "{%0,%1,%2,%3}, {%4,%5,%6,%7}, {%8,%9}, {%0,%1,%2,%3};"
        : "+f"(c0), "+f"(c1), "+f"(c2), "+f"(c3)
        : "r"(a0), "r"(a1), "r"(a2), "r"(a3), "r"(b0), "r"(b1));
}
__device__ __forceinline__ void split_bf16(float x, __nv_bfloat16& h, __nv_bfloat16& l) {
    h = __float2bfloat16(x);
    l = __float2bfloat16(x - __bfloat162float(h));
}

// ---------------------------------------------------------------------------
// fold1: P = W @ Wa (128x128), q = W @ ba   for adj/dis
// ---------------------------------------------------------------------------
__global__ void fold1_kernel(const float* __restrict__ W_adj,
                             const float* __restrict__ Wa_adj,
                             const float* __restrict__ ba_adj,
                             const float* __restrict__ W_dis,
                             const float* __restrict__ Wa_dis,
                             const float* __restrict__ ba_dis) {
    const int g = blockIdx.x;
    const int which = blockIdx.y;
    const int d = threadIdx.x;

    const float* W  = which ? W_dis  : W_adj;
    const float* Wa = which ? Wa_dis : Wa_adj;
    const float* ba = which ? ba_dis : ba_adj;
    float* P = which ? g_Pdis : g_Padj;
    float* q = which ? g_qdis : g_qadj;

    float acc = 0.f;
#pragma unroll 8
    for (int e = 0; e < 128; e++)
        acc += W[g * 128 + e] * Wa[e * 128 + d];
    P[g * 128 + d] = acc;

    __shared__ float red[128];
    red[d] = W[g * 128 + d] * ba[d];
    __syncthreads();
#pragma unroll
    for (int s = 64; s > 0; s >>= 1) {
        if (d < s) red[d] += red[d + s];
        __syncthreads();
    }
    if (d == 0) q[g] = red[0];
}

// ---------------------------------------------------------------------------
// fold2: folded A[n][k] -> bf16 hi/lo (row-major N x K), and c[n]
// ---------------------------------------------------------------------------
__global__ void fold2_kernel(const float* __restrict__ WC,
                             const float* __restrict__ W_self,
                             const float* __restrict__ bWC,
                             const float* __restrict__ bias) {
    const int n = blockIdx.x;
    const int k = threadIdx.x;

    float acc = 0.f;
    if (k < 128) {
#pragma unroll 8
        for (int e = 0; e < 128; e++)
            acc += WC[n * 384 + e] * W_self[e * 128 + k];
    } else if (k < 256) {
        const int kk = k - 128;
#pragma unroll 8
        for (int g = 0; g < 128; g++)
            acc += WC[n * 384 + 128 + g] * g_Padj[g * 128 + kk];
    } else {
        const int kk = k - 256;
#pragma unroll 8
        for (int g = 0; g < 128; g++)
            acc += WC[n * 384 + 256 + g] * g_Pdis[g * 128 + kk];
    }
    __nv_bfloat16 h, l;
    split_bf16(acc, h, l);
    g_Bhi[n * 384 + k] = h;
    g_Blo[n * 384 + k] = l;

    float cp = 0.f;
    if (k >= 128 && k < 256) cp = WC[n * 384 + k] * g_qadj[k - 128];
    else if (k >= 256)       cp = WC[n * 384 + k] * g_qdis[k - 256];

    __shared__ float red[384];
    red[k] = cp;
    __syncthreads();
    if (k < 128) red[k] = red[k] + red[k + 128] + red[k + 256];
    __syncthreads();
#pragma unroll
    for (int s = 64; s > 0; s >>= 1) {
        if (k < s) red[k] += red[k + s];
        __syncthreads();
    }
    if (k == 0) g_c[n] = red[0] + bWC[n] + bias[n];
}

// ---------------------------------------------------------------------------
// gather_mean: X[u] = [self | mean_adj | mean_dis] -> bf16 hi/lo
// DRAM-roofline kernel (~537 MB of random coalesced 512B rows)
// ---------------------------------------------------------------------------
__global__ void gather_mean_kernel(const float* __restrict__ emb,
                                   const int* __restrict__ uid,
                                   const int* __restrict__ adj,
                                   const int* __restrict__ dis) {
    const int u = blockIdx.x;
    const int t = threadIdx.x;

    __shared__ int sa[K_NEIGH];
    __shared__ int sd[K_NEIGH];
    __shared__ int sself;
    if (t < 32)       sa[t]      = adj[u * K_NEIGH + t];
    else if (t < 64)  sd[t - 32] = dis[u * K_NEIGH + (t - 32)];
    else if (t == 64) sself      = uid[u];
    __syncthreads();

    float acc_a = 0.f, acc_d = 0.f;
#pragma unroll
    for (int k = 0; k < K_NEIGH; k++) {
        acc_a += emb[(size_t)sa[k] * D_IN + t];
        acc_d += emb[(size_t)sd[k] * D_IN + t];
    }
    const float selfv = emb[(size_t)sself * D_IN + t];
    acc_a *= (1.0f / 32.0f);
    acc_d *= (1.0f / 32.0f);

    const size_t r = (size_t)u * 384;
    __nv_bfloat16 h, l;
    split_bf16(selfv, h, l);  g_Xhi[r + t] = h;        g_Xlo[r + t] = l;
    split_bf16(acc_a, h, l);  g_Xhi[r + 128 + t] = h;  g_Xlo[r + 128 + t] = l;
    split_bf16(acc_d, h, l);  g_Xhi[r + 256 + t] = h;  g_Xlo[r + 256 + t] = l;
}

// ---------------------------------------------------------------------------
// GEMM: Y = leaky( X[16384,384] @ A^T + c ) via mma.sync bf16x3
// Virtual K' = 1152: products (Xhi,Bhi) (Xhi,Blo) (Xlo,Bhi).
// CTA tile 128x128, 8 warps (4m x 2n), warp tile 32x64, k-chunk 32,
// cp.async double buffer, padded 80B smem rows (conflict-free ldmatrix).
// ---------------------------------------------------------------------------
#define SPAD 40                       // bf16 elems per smem row (80 B)
#define TILE_BYTES (128 * SPAD * 2)   // 10240 B per operand buffer

__global__ __launch_bounds__(256, 2) void gemm_hmma_kernel() {
    __shared__ __align__(16) __nv_bfloat16 As[2][128 * SPAD];
    __shared__ __align__(16) __nv_bfloat16 Bs[2][128 * SPAD];

    const int t = threadIdx.x;
    const int lane = t & 31;
    const int wid = t >> 5;
    const int wm = wid & 3;          // warp m index (0..3) -> 32 rows each
    const int wn = wid >> 2;         // warp n index (0..1) -> 64 cols each
    const int n0 = blockIdx.x * 128;
    const int m0 = blockIdx.y * 128;

    const uint32_t as_base = smem_u32(As);
    const uint32_t bs_base = smem_u32(Bs);

    // per-thread gl->smem load coords (2 x 16B per operand per iter)
    const int row_a = t >> 2;          // 0..63 (first half), +64 second
    const int ch    = t & 3;           // 16B chunk in 64B row

    // ldmatrix per-lane address offsets (bytes)
    const uint32_t a_lm = (uint32_t)((lane & 15) * (SPAD * 2) + (lane >> 4) * 16);
    const uint32_t b_lm = (uint32_t)(((lane & 7) + ((lane >> 4) << 3)) * (SPAD * 2)
                                     + (((lane >> 3) & 1) << 4));

    float acc[2][8][4];
#pragma unroll
    for (int i = 0; i < 2; i++)
#pragma unroll
        for (int j = 0; j < 8; j++)
#pragma unroll
            for (int q = 0; q < 4; q++) acc[i][j][q] = 0.f;

    // ---- load one k-chunk (iteration it) into buffer buf ----
    auto load_iter = [&](int it, int buf) {
        const int p  = it / 12;                 // product index
        const int kc = (it % 12) * 32;          // k offset within 384
        const __nv_bfloat16* Asrc = (p < 2) ? g_Xhi : g_Xlo;
        const __nv_bfloat16* Bsrc = (p == 1) ? g_Blo : g_Bhi;
#pragma unroll
        for (int j = 0; j < 2; j++) {
            const int r = row_a + j * 64;
            cp_async16(as_base + buf * TILE_BYTES + (uint32_t)(r * (SPAD * 2) + ch * 16),
                       Asrc + (size_t)(m0 + r) * 384 + kc + ch * 8);
            cp_async16(bs_base + buf * TILE_BYTES + (uint32_t)(r * (SPAD * 2) + ch * 16),
                       Bsrc + (size_t)(n0 + r) * 384 + kc + ch * 8);
        }
        cp_commit();
    };

    load_iter(0, 0);

    for (int it = 0; it < 36; it++) {
        const int buf = it & 1;
        if (it + 1 < 36) load_iter(it + 1, buf ^ 1);
        if (it + 1 < 36) cp_wait<1>(); else cp_wait<0>();
        __syncthreads();

        const uint32_t a_tile = as_base + buf * TILE_BYTES
                              + (uint32_t)(wm * 32 * (SPAD * 2)) + a_lm;
        const uint32_t b_tile = bs_base + buf * TILE_BYTES
                              + (uint32_t)(wn * 64 * (SPAD * 2)) + b_lm;

#pragma unroll
        for (int ks = 0; ks < 2; ks++) {
            uint32_t af[2][4];
            uint32_t bf_[4][4];
#pragma unroll
            for (int mi = 0; mi < 2; mi++)
                ldsm_x4(af[mi][0], af[mi][1], af[mi][2], af[mi][3],
                        a_tile + (uint32_t)(mi * 16 * (SPAD * 2) + ks * 32));
#pragma unroll
            for (int bj = 0; bj < 4; bj++)
                ldsm_x4(bf_[bj][0], bf_[bj][1], bf_[bj][2], bf_[bj][3],
                        b_tile + (uint32_t)(bj * 16 * (SPAD * 2) + ks * 32));
#pragma unroll
            for (int mi = 0; mi < 2; mi++)
#pragma unroll
                for (int nj = 0; nj < 8; nj++)
                    mma16816(acc[mi][nj][0], acc[mi][nj][1],
                             acc[mi][nj][2], acc[mi][nj][3],
                             af[mi][0], af[mi][1], af[mi][2], af[mi][3],
                             bf_[nj >> 1][(nj & 1) * 2], bf_[nj >> 1][(nj & 1) * 2 + 1]);
        }
        __syncthreads();
    }

    // ---- epilogue: += c, leaky relu, store to g_Y ----
    float cv[8][2];
#pragma unroll
    for (int nj = 0; nj < 8; nj++) {
        const int col = n0 + wn * 64 + nj * 8 + (lane & 3) * 2;
        cv[nj][0] = g_c[col];
        cv[nj][1] = g_c[col + 1];
    }
#pragma unroll
    for (int mi = 0; mi < 2; mi++) {
        const int row = m0 + wm * 32 + mi * 16 + (lane >> 2);
#pragma unroll
        for (int nj = 0; nj < 8; nj++) {
            const int col = n0 + wn * 64 + nj * 8 + (lane & 3) * 2;
            float y0 = acc[mi][nj][0] + cv[nj][0];
            float y1 = acc[mi][nj][1] + cv[nj][1];
            float y2 = acc[mi][nj][2] + cv[nj][0];
            float y3 = acc[mi][nj][3] + cv[nj][1];
            y0 = (y0 > 0.f) ? y0 : 0.2f * y0;
            y1 = (y1 > 0.f) ? y1 : 0.2f * y1;
            y2 = (y2 > 0.f) ? y2 : 0.2f * y2;
            y3 = (y3 > 0.f) ? y3 : 0.2f * y3;
            *(float2*)&g_Y[(size_t)row * 384 + col]       = make_float2(y0, y1);
            *(float2*)&g_Y[(size_t)(row + 8) * 384 + col] = make_float2(y2, y3);
        }
    }
}

// ---------------------------------------------------------------------------
// norm_gather: out[b] = normalize(Y[nodes_idx[b]])
// ---------------------------------------------------------------------------
__global__ void norm_gather_kernel(const int* __restrict__ nodes_idx,
                                   float* __restrict__ out) {
    const int w = threadIdx.x >> 5;
    const int l = threadIdx.x & 31;
    const int b = blockIdx.x * 8 + w;
    const int u = nodes_idx[b];

    const float4* yr = (const float4*)(g_Y + (size_t)u * 384);
    float4 v0 = yr[l];
    float4 v1 = yr[l + 32];
    float4 v2 = yr[l + 64];

    float s = v0.x * v0.x + v0.y * v0.y + v0.z * v0.z + v0.w * v0.w
            + v1.x * v1.x + v1.y * v1.y + v1.z * v1.z + v1.w * v1.w
            + v2.x * v2.x + v2.y * v2.y + v2.z * v2.z + v2.w * v2.w;
#pragma unroll
    for (int off = 16; off > 0; off >>= 1)
        s += __shfl_xor_sync(0xffffffffu, s, off);

    const float inv = 1.0f / fmaxf(sqrtf(s), 1e-12f);

    float4* o = (float4*)(out + (size_t)b * 384);
    v0.x *= inv; v0.y *= inv; v0.z *= inv; v0.w *= inv;
    v1.x *= inv; v1.y *= inv; v1.z *= inv; v1.w *= inv;
    v2.x *= inv; v2.y *= inv; v2.z *= inv; v2.w *= inv;
    o[l]      = v0;
    o[l + 32] = v1;
    o[l + 64] = v2;
}

// ---------------------------------------------------------------------------
extern "C" void kernel_launch(void* const* d_in, const int* in_sizes, int n_in,
                              void* d_out, int out_size) {
    const float* emb    = (const float*)d_in[0];
    const float* Wa_adj = (const float*)d_in[1];
    const float* ba_adj = (const float*)d_in[2];
    const float* Wa_dis = (const float*)d_in[3];
    const float* ba_dis = (const float*)d_in[4];
    const float* W_self = (const float*)d_in[5];
    const float* W_adj  = (const float*)d_in[6];
    const float* W_dis  = (const float*)d_in[7];
    const float* WC     = (const float*)d_in[8];
    const float* bWC    = (const float*)d_in[9];
    const float* bias   = (const float*)d_in[10];
    const int* uid      = (const int*)d_in[11];
    const int* adj      = (const int*)d_in[12];
    const int* dis      = (const int*)d_in[13];
    const int* nidx     = (const int*)d_in[14];
    float* out          = (float*)d_out;

    fold1_kernel<<<dim3(128, 2), 128>>>(W_adj, Wa_adj, ba_adj,
                                        W_dis, Wa_dis, ba_dis);
    fold2_kernel<<<384, 384>>>(WC, W_self, bWC, bias);
    gather_mean_kernel<<<U_NODES, 128>>>(emb, uid, adj, dis);
    gemm_hmma_kernel<<<dim3(3, 128), 256>>>();
    norm_gather_kernel<<<B_OUT / 8, 256>>>(nidx, out);
}